// round 12
// baseline (speedup 1.0000x reference)
#include <cuda_runtime.h>
#include <cuda_bf16.h>
#include <cstdint>

#define SAMP_PER_T  16         // int4 per thread in the single sample block
#define MAIN_BLOCKS 1184
#define TPB         256

// Device-global scratch (no allocations). Counter self-resets every launch;
// all other cells are rewritten before being read -> deterministic.
__device__ unsigned g_guess_pack;
__device__ unsigned g_partial[MAIN_BLOCKS];
__device__ unsigned g_act_pack;
__device__ unsigned g_mismatch;
__device__ unsigned g_mcnt;

// ---------------------------------------------------------------------------
// Robust small-integer scalar decode (int32/int64/float32/float64).
// ---------------------------------------------------------------------------
__device__ __forceinline__ int decode_scalar(const int* p, int dflt) {
    if (p == nullptr) return dflt;
    int w0 = p[0];
    if (w0 >= -1000000 && w0 <= 1000000) {
        if (w0 != 0) return w0;
        int w1 = p[1];
        if (w1 == 0) return 0;
        double d = __hiloint2double(w1, w0);
        if (d >= -1e6 && d <= 1e6) return (int)d;
        return 0;
    }
    float f = __int_as_float(w0);
    if (f >= -1e6f && f <= 1e6f) return (int)f;
    int w1 = p[1];
    double d = __hiloint2double(w1, w0);
    if (d >= -1e6 && d <= 1e6) return (int)d;
    return dflt;
}

// Transform descriptor: pack = mode | (shift << 2)
//   mode 0 = zeros (bw==0), 1 = int8-wrap trunc (shift<1), 2 = psto(shift)
__device__ __forceinline__ unsigned make_pack(unsigned rng, int mu) {
    if (rng == 0u) return 0u;
    int bw = (int)ceilf(log2f(fmaxf((float)rng, 1.0f)));
    int shift = bw - mu;
    if (shift < 1) return 1u;
    return 2u | ((unsigned)shift << 2);
}

// Pseudo-stochastic shift quantizer (bit-exact vs reference, s >= 1).
__device__ __forceinline__ int uw_psto(int x, int s) {
    int rt   = x >> s;
    int prob = x & ((1 << s) - 1);
    int hs   = s >> 1;
    int qprob = prob >> hs;
    int prn   = (prob & ((1 << hs) - 1)) * (1 + (s & 1));
    int sgn   = (x > 0) - (x < 0);
    int dec   = (qprob <= prn) ? 0 : sgn;
    return min(127, max(-127, rt + dec));
}

__device__ __forceinline__ unsigned max4abs(int4 v) {
    unsigned a0 = (unsigned)(v.x < 0 ? -v.x : v.x);
    unsigned a1 = (unsigned)(v.y < 0 ? -v.y : v.y);
    unsigned a2 = (unsigned)(v.z < 0 ? -v.z : v.z);
    unsigned a3 = (unsigned)(v.w < 0 ? -v.w : v.w);
    return max(max(a0, a1), max(a2, a3));
}

__device__ __forceinline__ void uw_apply(int4 gv, int4 wv, int mode, int s,
                                         float4& ow, float4& og) {
    int gx[4] = { gv.x, gv.y, gv.z, gv.w };
    int wi[4] = { wv.x, wv.y, wv.z, wv.w };
    float o_g[4], o_w[4];
#pragma unroll
    for (int k = 0; k < 4; k++) {
        int gq;
        if (mode == 0)      gq = 0;
        else if (mode == 1) gq = (int)(signed char)gx[k];   // wraps like astype(int8)
        else                gq = uw_psto(gx[k], s);
        int nw = wi[k] - gq;
        nw = min(127, max(-127, nw));
        o_g[k] = (float)gq;
        o_w[k] = (float)nw;
    }
    ow = make_float4(o_w[0], o_w[1], o_w[2], o_w[3]);
    og = make_float4(o_g[0], o_g[1], o_g[2], o_g[3]);
}

__device__ __forceinline__ unsigned block_reduce_max256(unsigned m, unsigned* s_red) {
    m = __reduce_max_sync(0xffffffffu, m);
    int lane = threadIdx.x & 31;
    int wid  = threadIdx.x >> 5;
    if (lane == 0) s_red[wid] = m;
    __syncthreads();
    unsigned v = 0u;
    if (wid == 0) {
        v = (lane < (int)(blockDim.x >> 5)) ? s_red[lane] : 0u;
        v = __reduce_max_sync(0xffffffffu, v);
    }
    return v;  // valid in warp 0
}

// ---------------------------------------------------------------------------
// K1: SINGLE-BLOCK sample. 256 threads x SAMP_PER_T int4, organized as
// SAMP_PER_T coalesced 4KB groups spread evenly across the array. One block
// -> no atomics, no fence, no cross-block scan. Writes g_guess_pack.
// ---------------------------------------------------------------------------
__global__ void uw_sample_kernel(const int4* __restrict__ g, long n4,
                                 long group_stride,
                                 const int* __restrict__ p_mu) {
    __shared__ unsigned s_red[32];
    unsigned m = 0u;
#pragma unroll
    for (int k = 0; k < SAMP_PER_T; k++) {
        long idx = (long)k * group_stride + threadIdx.x;   // coalesced group
        if (idx < n4) m = max(m, max4abs(__ldg(&g[idx])));
    }
    unsigned rng = block_reduce_max256(m, s_red);
    if (threadIdx.x == 0)
        g_guess_pack = make_pack(rng, decode_scalar(p_mu, 7));
}

// ---------------------------------------------------------------------------
// K2: fused main pass, grid-stride (MAIN_BLOCKS), 4-way batched loads for
// MLP. Writes outputs with the GUESSED transform; true per-block max ->
// g_partial. Last finishing block reduces partials -> actual pack, mismatch
// flag, grad_exp.
// ---------------------------------------------------------------------------
__global__ void __launch_bounds__(TPB, 8) uw_main_kernel(
    const int4* __restrict__ w4,
    const int4* __restrict__ g4,
    float4* __restrict__ ow4,
    float4* __restrict__ og4,
    const int* __restrict__ p_err_exp,
    const int* __restrict__ p_act_in_exp,
    const int* __restrict__ p_mu,
    float* __restrict__ out_exp,
    long n4)
{
    __shared__ unsigned s_red[32];
    __shared__ unsigned s_last;

    unsigned pack = g_guess_pack;
    int mode = (int)(pack & 3u);
    int s    = (int)(pack >> 2);

    const long S  = (long)gridDim.x * blockDim.x;
    long i = (long)blockIdx.x * blockDim.x + threadIdx.x;

    unsigned m = 0u;
    // 4-way batched: 8 independent loads in flight per iteration.
    for (; i + 3 * S < n4; i += 4 * S) {
        int4 g0 = __ldg(&g4[i]);
        int4 g1 = __ldg(&g4[i +     S]);
        int4 g2 = __ldg(&g4[i + 2 * S]);
        int4 g3 = __ldg(&g4[i + 3 * S]);
        int4 w0 = __ldg(&w4[i]);
        int4 w1 = __ldg(&w4[i +     S]);
        int4 w2 = __ldg(&w4[i + 2 * S]);
        int4 w3 = __ldg(&w4[i + 3 * S]);
        m = max(m, max(max(max4abs(g0), max4abs(g1)),
                       max(max4abs(g2), max4abs(g3))));
        float4 ow, og;
        uw_apply(g0, w0, mode, s, ow, og); ow4[i]         = ow; og4[i]         = og;
        uw_apply(g1, w1, mode, s, ow, og); ow4[i +     S] = ow; og4[i +     S] = og;
        uw_apply(g2, w2, mode, s, ow, og); ow4[i + 2 * S] = ow; og4[i + 2 * S] = og;
        uw_apply(g3, w3, mode, s, ow, og); ow4[i + 3 * S] = ow; og4[i + 3 * S] = og;
    }
    for (; i < n4; i += S) {
        int4 gv = __ldg(&g4[i]);
        int4 wv = __ldg(&w4[i]);
        m = max(m, max4abs(gv));
        float4 ow, og;
        uw_apply(gv, wv, mode, s, ow, og);
        ow4[i] = ow;
        og4[i] = og;
    }

    unsigned bm = block_reduce_max256(m, s_red);
    if (threadIdx.x == 0) {
        g_partial[blockIdx.x] = bm;
        __threadfence();
        unsigned t = atomicAdd(&g_mcnt, 1u);
        s_last = (t == (unsigned)(gridDim.x - 1)) ? 1u : 0u;
    }
    __syncthreads();
    if (s_last) {
        unsigned m0 = 0u, m1 = 0u, m2 = 0u, m3 = 0u;
        for (int j = threadIdx.x * 4; j < MAIN_BLOCKS; j += blockDim.x * 4) {
            m0 = max(m0, __ldcg(&g_partial[j]));
            if (j + 1 < MAIN_BLOCKS) m1 = max(m1, __ldcg(&g_partial[j + 1]));
            if (j + 2 < MAIN_BLOCKS) m2 = max(m2, __ldcg(&g_partial[j + 2]));
            if (j + 3 < MAIN_BLOCKS) m3 = max(m3, __ldcg(&g_partial[j + 3]));
        }
        unsigned mm = max(max(m0, m1), max(m2, m3));
        __syncthreads();                       // s_red reuse
        unsigned rng = block_reduce_max256(mm, s_red);
        if (threadIdx.x == 0) {
            int mu = decode_scalar(p_mu, 7);
            unsigned act = make_pack(rng, mu);
            g_act_pack = act;
            g_mismatch = (act != pack) ? 1u : 0u;
            int amode = (int)(act & 3u);
            int gs    = (amode == 2) ? (int)(act >> 2) : 0;
            int ee = decode_scalar(p_err_exp, -10);
            int ae = decode_scalar(p_act_in_exp, -7);
            *out_exp = (float)(ee + gs + ae);
            g_mcnt = 0u;                        // self-reset for next launch
        }
    }
}

// ---------------------------------------------------------------------------
// K3: fixup. If the guess matched (overwhelmingly likely), every block exits
// immediately. Otherwise rewrites all outputs with the actual transform.
// ---------------------------------------------------------------------------
__global__ void uw_fixup_kernel(
    const int4* __restrict__ w4,
    const int4* __restrict__ g4,
    float4* __restrict__ ow4,
    float4* __restrict__ og4,
    long n4)
{
    if (g_mismatch == 0u) return;
    unsigned pack = g_act_pack;
    int mode = (int)(pack & 3u);
    int s    = (int)(pack >> 2);

    long i0     = (long)blockIdx.x * blockDim.x + threadIdx.x;
    long stride = (long)gridDim.x * blockDim.x;
    for (long i = i0; i < n4; i += stride) {
        int4 gv = __ldg(&g4[i]);
        int4 wv = __ldg(&w4[i]);
        float4 ow, og;
        uw_apply(gv, wv, mode, s, ow, og);
        ow4[i] = ow;
        og4[i] = og;
    }
}

// ---------------------------------------------------------------------------
// Launch. Inputs: weight int32[N] (promoted int8), grad int32[N],
// err_exp, act_in_exp, mu (int32 scalars).
// Output: float32[2N+1] = concat(new_weight, grad, grad_exp).
// ---------------------------------------------------------------------------
extern "C" void kernel_launch(void* const* d_in, const int* in_sizes, int n_in,
                              void* d_out, int out_size)
{
    const int4* w4 = (const int4*)d_in[0];
    const int4* g4 = (const int4*)d_in[1];
    const int* p_err = (n_in > 2) ? (const int*)d_in[2] : nullptr;
    const int* p_act = (n_in > 3) ? (const int*)d_in[3] : nullptr;
    const int* p_mu  = (n_in > 4) ? (const int*)d_in[4] : nullptr;

    long N  = (long)in_sizes[0];
    long n4 = N >> 2;

    float* out   = (float*)d_out;
    float4* ow4  = (float4*)out;
    float4* og4  = (float4*)(out + N);
    float* out_e = out + 2 * N;

    // SAMP_PER_T coalesced groups spread evenly across the array.
    long group_stride = n4 / SAMP_PER_T;
    if (group_stride < TPB) group_stride = TPB;

    uw_sample_kernel<<<1, TPB>>>(g4, n4, group_stride, p_mu);
    uw_main_kernel<<<MAIN_BLOCKS, TPB>>>(w4, g4, ow4, og4,
                                         p_err, p_act, p_mu, out_e, n4);
    uw_fixup_kernel<<<MAIN_BLOCKS, TPB>>>(w4, g4, ow4, og4, n4);
}

// round 13
// speedup vs baseline: 1.4192x; 1.4192x over previous
#include <cuda_runtime.h>
#include <cuda_bf16.h>
#include <cstdint>

#define MAIN_BLOCKS 1184
#define TPB         256

// Device-global scratch (no allocations). All state self-resets every launch
// (last block restores counters/min/max) -> deterministic, graph-safe.
__device__ unsigned g_partial[MAIN_BLOCKS];
__device__ unsigned g_act_pack;
__device__ unsigned g_mismatch;
__device__ unsigned g_mcnt    = 0u;
__device__ unsigned g_packmin = 0xFFFFFFFFu;
__device__ unsigned g_packmax = 0u;

// ---------------------------------------------------------------------------
// Robust small-integer scalar decode (int32/int64/float32/float64).
// ---------------------------------------------------------------------------
__device__ __forceinline__ int decode_scalar(const int* p, int dflt) {
    if (p == nullptr) return dflt;
    int w0 = p[0];
    if (w0 >= -1000000 && w0 <= 1000000) {
        if (w0 != 0) return w0;
        int w1 = p[1];
        if (w1 == 0) return 0;
        double d = __hiloint2double(w1, w0);
        if (d >= -1e6 && d <= 1e6) return (int)d;
        return 0;
    }
    float f = __int_as_float(w0);
    if (f >= -1e6f && f <= 1e6f) return (int)f;
    int w1 = p[1];
    double d = __hiloint2double(w1, w0);
    if (d >= -1e6 && d <= 1e6) return (int)d;
    return dflt;
}

// Transform descriptor: pack = mode | (shift << 2)
//   mode 0 = zeros (bw==0), 1 = int8-wrap trunc (shift<1), 2 = psto(shift)
__device__ __forceinline__ unsigned make_pack(unsigned rng, int mu) {
    if (rng == 0u) return 0u;
    int bw = (int)ceilf(log2f(fmaxf((float)rng, 1.0f)));
    int shift = bw - mu;
    if (shift < 1) return 1u;
    return 2u | ((unsigned)shift << 2);
}

// Pseudo-stochastic shift quantizer (bit-exact vs reference, s >= 1).
__device__ __forceinline__ int uw_psto(int x, int s) {
    int rt   = x >> s;
    int prob = x & ((1 << s) - 1);
    int hs   = s >> 1;
    int qprob = prob >> hs;
    int prn   = (prob & ((1 << hs) - 1)) * (1 + (s & 1));
    int sgn   = (x > 0) - (x < 0);
    int dec   = (qprob <= prn) ? 0 : sgn;
    return min(127, max(-127, rt + dec));
}

__device__ __forceinline__ unsigned max4abs(int4 v) {
    unsigned a0 = (unsigned)(v.x < 0 ? -v.x : v.x);
    unsigned a1 = (unsigned)(v.y < 0 ? -v.y : v.y);
    unsigned a2 = (unsigned)(v.z < 0 ? -v.z : v.z);
    unsigned a3 = (unsigned)(v.w < 0 ? -v.w : v.w);
    return max(max(a0, a1), max(a2, a3));
}

__device__ __forceinline__ void uw_apply(int4 gv, int4 wv, int mode, int s,
                                         float4& ow, float4& og) {
    int gx[4] = { gv.x, gv.y, gv.z, gv.w };
    int wi[4] = { wv.x, wv.y, wv.z, wv.w };
    float o_g[4], o_w[4];
#pragma unroll
    for (int k = 0; k < 4; k++) {
        int gq;
        if (mode == 0)      gq = 0;
        else if (mode == 1) gq = (int)(signed char)gx[k];   // wraps like astype(int8)
        else                gq = uw_psto(gx[k], s);
        int nw = wi[k] - gq;
        nw = min(127, max(-127, nw));
        o_g[k] = (float)gq;
        o_w[k] = (float)nw;
    }
    ow = make_float4(o_w[0], o_w[1], o_w[2], o_w[3]);
    og = make_float4(o_g[0], o_g[1], o_g[2], o_g[3]);
}

__device__ __forceinline__ unsigned block_reduce_max256(unsigned m, unsigned* s_red) {
    m = __reduce_max_sync(0xffffffffu, m);
    int lane = threadIdx.x & 31;
    int wid  = threadIdx.x >> 5;
    if (lane == 0) s_red[wid] = m;
    __syncthreads();
    unsigned v = 0u;
    if (wid == 0) {
        v = (lane < (int)(blockDim.x >> 5)) ? s_red[lane] : 0u;
        v = __reduce_max_sync(0xffffffffu, v);
    }
    return v;  // valid in warp 0
}

// ---------------------------------------------------------------------------
// K1: single fused main pass with PER-BLOCK SELF-GUESS.
//   Prologue: each block loads its first 4-way batch, block-reduces its max
//   (16K int32 sample) -> its own guessed pack; applies it to the batch it
//   already holds, then streams the rest. True per-block max -> g_partial.
//   Every block publishes its pack via atomicMin/Max; the last finishing
//   block derives the ACTUAL pack from partials, verifies all blocks agreed
//   with it, writes grad_exp, raises g_mismatch otherwise, resets state.
// ---------------------------------------------------------------------------
__global__ void uw_main_kernel(
    const int4* __restrict__ w4,
    const int4* __restrict__ g4,
    float4* __restrict__ ow4,
    float4* __restrict__ og4,
    const int* __restrict__ p_err_exp,
    const int* __restrict__ p_act_in_exp,
    const int* __restrict__ p_mu,
    float* __restrict__ out_exp,
    long n4)
{
    __shared__ unsigned s_red[32];
    __shared__ unsigned s_pack;
    __shared__ unsigned s_last;

    const long S  = (long)gridDim.x * blockDim.x;
    const long i0 = (long)blockIdx.x * blockDim.x + threadIdx.x;
    int mu = decode_scalar(p_mu, 7);

    unsigned m = 0u;
    long i = i0;
    int4 g0, g1, g2, g3, w0, w1, w2, w3;
    const bool full = (i + 3 * S < n4);

    // ---- Prologue: first batch max (loads kept live in registers) ----
    if (full) {
        g0 = __ldg(&g4[i]);
        g1 = __ldg(&g4[i +     S]);
        g2 = __ldg(&g4[i + 2 * S]);
        g3 = __ldg(&g4[i + 3 * S]);
        w0 = __ldg(&w4[i]);
        w1 = __ldg(&w4[i +     S]);
        w2 = __ldg(&w4[i + 2 * S]);
        w3 = __ldg(&w4[i + 3 * S]);
        m = max(max(max4abs(g0), max4abs(g1)),
                max(max4abs(g2), max4abs(g3)));
    } else {
        for (long j = i; j < n4; j += S)
            m = max(m, max4abs(__ldg(&g4[j])));
    }
    {
        unsigned bm = block_reduce_max256(m, s_red);
        if (threadIdx.x == 0) s_pack = make_pack(bm, mu);
        __syncthreads();
    }
    const unsigned pack = s_pack;
    const int mode = (int)(pack & 3u);
    const int s    = (int)(pack >> 2);

    // ---- Main stream ----
    if (full) {
        float4 ow, og;
        uw_apply(g0, w0, mode, s, ow, og); ow4[i]         = ow; og4[i]         = og;
        uw_apply(g1, w1, mode, s, ow, og); ow4[i +     S] = ow; og4[i +     S] = og;
        uw_apply(g2, w2, mode, s, ow, og); ow4[i + 2 * S] = ow; og4[i + 2 * S] = og;
        uw_apply(g3, w3, mode, s, ow, og); ow4[i + 3 * S] = ow; og4[i + 3 * S] = og;
        i += 4 * S;
        for (; i + 3 * S < n4; i += 4 * S) {
            int4 a0 = __ldg(&g4[i]);
            int4 a1 = __ldg(&g4[i +     S]);
            int4 a2 = __ldg(&g4[i + 2 * S]);
            int4 a3 = __ldg(&g4[i + 3 * S]);
            int4 b0 = __ldg(&w4[i]);
            int4 b1 = __ldg(&w4[i +     S]);
            int4 b2 = __ldg(&w4[i + 2 * S]);
            int4 b3 = __ldg(&w4[i + 3 * S]);
            m = max(m, max(max(max4abs(a0), max4abs(a1)),
                           max(max4abs(a2), max4abs(a3))));
            uw_apply(a0, b0, mode, s, ow, og); ow4[i]         = ow; og4[i]         = og;
            uw_apply(a1, b1, mode, s, ow, og); ow4[i +     S] = ow; og4[i +     S] = og;
            uw_apply(a2, b2, mode, s, ow, og); ow4[i + 2 * S] = ow; og4[i + 2 * S] = og;
            uw_apply(a3, b3, mode, s, ow, og); ow4[i + 3 * S] = ow; og4[i + 3 * S] = og;
        }
        for (; i < n4; i += S) {
            int4 gv = __ldg(&g4[i]);
            int4 wv = __ldg(&w4[i]);
            m = max(m, max4abs(gv));
            uw_apply(gv, wv, mode, s, ow, og);
            ow4[i] = ow;
            og4[i] = og;
        }
    } else {
        // Rare tail path: m already covers all elements; re-load and apply.
        for (long j = i0; j < n4; j += S) {
            int4 gv = __ldg(&g4[j]);
            int4 wv = __ldg(&w4[j]);
            float4 ow, og;
            uw_apply(gv, wv, mode, s, ow, og);
            ow4[j] = ow;
            og4[j] = og;
        }
    }

    // ---- Epilogue: publish true max + pack; last block verifies ----
    unsigned bm = block_reduce_max256(m, s_red);
    if (threadIdx.x == 0) {
        g_partial[blockIdx.x] = bm;
        if (i0 < n4) {                       // only blocks that did work vote
            atomicMin(&g_packmin, pack);
            atomicMax(&g_packmax, pack);
        }
        __threadfence();
        unsigned t = atomicAdd(&g_mcnt, 1u);
        s_last = (t == (unsigned)(gridDim.x - 1)) ? 1u : 0u;
    }
    __syncthreads();
    if (s_last) {
        unsigned m0 = 0u, m1 = 0u, m2 = 0u, m3 = 0u;
        for (int j = threadIdx.x * 4; j < MAIN_BLOCKS; j += blockDim.x * 4) {
            m0 = max(m0, __ldcg(&g_partial[j]));
            if (j + 1 < MAIN_BLOCKS) m1 = max(m1, __ldcg(&g_partial[j + 1]));
            if (j + 2 < MAIN_BLOCKS) m2 = max(m2, __ldcg(&g_partial[j + 2]));
            if (j + 3 < MAIN_BLOCKS) m3 = max(m3, __ldcg(&g_partial[j + 3]));
        }
        unsigned mm = max(max(m0, m1), max(m2, m3));
        __syncthreads();                       // s_red reuse
        unsigned rng = block_reduce_max256(mm, s_red);
        if (threadIdx.x == 0) {
            unsigned act = make_pack(rng, mu);
            unsigned pmin = atomicAdd(&g_packmin, 0u);
            unsigned pmax = atomicAdd(&g_packmax, 0u);
            g_act_pack = act;
            g_mismatch = (pmin != act || pmax != act) ? 1u : 0u;
            int amode = (int)(act & 3u);
            int gs    = (amode == 2) ? (int)(act >> 2) : 0;
            int ee = decode_scalar(p_err_exp, -10);
            int ae = decode_scalar(p_act_in_exp, -7);
            *out_exp = (float)(ee + gs + ae);
            // Self-reset for next launch.
            g_mcnt    = 0u;
            g_packmin = 0xFFFFFFFFu;
            g_packmax = 0u;
        }
    }
}

// ---------------------------------------------------------------------------
// K2: fixup. If every block agreed with the actual pack (overwhelmingly
// likely), all blocks exit immediately. Otherwise rewrites all outputs with
// the actual transform -> result always exactly correct.
// ---------------------------------------------------------------------------
__global__ void uw_fixup_kernel(
    const int4* __restrict__ w4,
    const int4* __restrict__ g4,
    float4* __restrict__ ow4,
    float4* __restrict__ og4,
    long n4)
{
    if (g_mismatch == 0u) return;
    unsigned pack = g_act_pack;
    int mode = (int)(pack & 3u);
    int s    = (int)(pack >> 2);

    long i0     = (long)blockIdx.x * blockDim.x + threadIdx.x;
    long stride = (long)gridDim.x * blockDim.x;
    for (long i = i0; i < n4; i += stride) {
        int4 gv = __ldg(&g4[i]);
        int4 wv = __ldg(&w4[i]);
        float4 ow, og;
        uw_apply(gv, wv, mode, s, ow, og);
        ow4[i] = ow;
        og4[i] = og;
    }
}

// ---------------------------------------------------------------------------
// Launch. Inputs: weight int32[N] (promoted int8), grad int32[N],
// err_exp, act_in_exp, mu (int32 scalars).
// Output: float32[2N+1] = concat(new_weight, grad, grad_exp).
// ---------------------------------------------------------------------------
extern "C" void kernel_launch(void* const* d_in, const int* in_sizes, int n_in,
                              void* d_out, int out_size)
{
    const int4* w4 = (const int4*)d_in[0];
    const int4* g4 = (const int4*)d_in[1];
    const int* p_err = (n_in > 2) ? (const int*)d_in[2] : nullptr;
    const int* p_act = (n_in > 3) ? (const int*)d_in[3] : nullptr;
    const int* p_mu  = (n_in > 4) ? (const int*)d_in[4] : nullptr;

    long N  = (long)in_sizes[0];
    long n4 = N >> 2;

    float* out   = (float*)d_out;
    float4* ow4  = (float4*)out;
    float4* og4  = (float4*)(out + N);
    float* out_e = out + 2 * N;

    uw_main_kernel<<<MAIN_BLOCKS, TPB>>>(w4, g4, ow4, og4,
                                         p_err, p_act, p_mu, out_e, n4);
    uw_fixup_kernel<<<MAIN_BLOCKS, TPB>>>(w4, g4, ow4, og4, n4);
}

// round 14
// speedup vs baseline: 1.4748x; 1.0391x over previous
#include <cuda_runtime.h>
#include <cuda_bf16.h>
#include <cstdint>

#define MAIN_BLOCKS 1184
#define TPB         256

// Device-global scratch (no allocations). All state self-resets every launch
// (last block restores it after use) -> deterministic, graph-safe.
__device__ unsigned g_act_rng  = 0u;
__device__ unsigned g_mcnt     = 0u;
__device__ unsigned g_packmin  = 0xFFFFFFFFu;
__device__ unsigned g_packmax  = 0u;

// ---------------------------------------------------------------------------
// Robust small-integer scalar decode (int32/int64/float32/float64).
// ---------------------------------------------------------------------------
__device__ __forceinline__ int decode_scalar(const int* p, int dflt) {
    if (p == nullptr) return dflt;
    int w0 = p[0];
    if (w0 >= -1000000 && w0 <= 1000000) {
        if (w0 != 0) return w0;
        int w1 = p[1];
        if (w1 == 0) return 0;
        double d = __hiloint2double(w1, w0);
        if (d >= -1e6 && d <= 1e6) return (int)d;
        return 0;
    }
    float f = __int_as_float(w0);
    if (f >= -1e6f && f <= 1e6f) return (int)f;
    int w1 = p[1];
    double d = __hiloint2double(w1, w0);
    if (d >= -1e6 && d <= 1e6) return (int)d;
    return dflt;
}

// Transform descriptor: pack = mode | (shift << 2)
//   mode 0 = zeros (bw==0), 1 = int8-wrap trunc (shift<1), 2 = psto(shift)
__device__ __forceinline__ unsigned make_pack(unsigned rng, int mu) {
    if (rng == 0u) return 0u;
    int bw = (int)ceilf(log2f(fmaxf((float)rng, 1.0f)));
    int shift = bw - mu;
    if (shift < 1) return 1u;
    return 2u | ((unsigned)shift << 2);
}

// Pseudo-stochastic shift quantizer (bit-exact vs reference, s >= 1).
__device__ __forceinline__ int uw_psto(int x, int s) {
    int rt   = x >> s;
    int prob = x & ((1 << s) - 1);
    int hs   = s >> 1;
    int qprob = prob >> hs;
    int prn   = (prob & ((1 << hs) - 1)) * (1 + (s & 1));
    int sgn   = (x > 0) - (x < 0);
    int dec   = (qprob <= prn) ? 0 : sgn;
    return min(127, max(-127, rt + dec));
}

__device__ __forceinline__ unsigned max4abs(int4 v) {
    unsigned a0 = (unsigned)(v.x < 0 ? -v.x : v.x);
    unsigned a1 = (unsigned)(v.y < 0 ? -v.y : v.y);
    unsigned a2 = (unsigned)(v.z < 0 ? -v.z : v.z);
    unsigned a3 = (unsigned)(v.w < 0 ? -v.w : v.w);
    return max(max(a0, a1), max(a2, a3));
}

__device__ __forceinline__ void uw_apply(int4 gv, int4 wv, int mode, int s,
                                         float4& ow, float4& og) {
    int gx[4] = { gv.x, gv.y, gv.z, gv.w };
    int wi[4] = { wv.x, wv.y, wv.z, wv.w };
    float o_g[4], o_w[4];
#pragma unroll
    for (int k = 0; k < 4; k++) {
        int gq;
        if (mode == 0)      gq = 0;
        else if (mode == 1) gq = (int)(signed char)gx[k];   // wraps like astype(int8)
        else                gq = uw_psto(gx[k], s);
        int nw = wi[k] - gq;
        nw = min(127, max(-127, nw));
        o_g[k] = (float)gq;
        o_w[k] = (float)nw;
    }
    ow = make_float4(o_w[0], o_w[1], o_w[2], o_w[3]);
    og = make_float4(o_g[0], o_g[1], o_g[2], o_g[3]);
}

__device__ __forceinline__ unsigned block_reduce_max256(unsigned m, unsigned* s_red) {
    m = __reduce_max_sync(0xffffffffu, m);
    int lane = threadIdx.x & 31;
    int wid  = threadIdx.x >> 5;
    if (lane == 0) s_red[wid] = m;
    __syncthreads();
    unsigned v = 0u;
    if (wid == 0) {
        v = (lane < (int)(blockDim.x >> 5)) ? s_red[lane] : 0u;
        v = __reduce_max_sync(0xffffffffu, v);
    }
    return v;  // valid in warp 0
}

// ---------------------------------------------------------------------------
// SINGLE fused kernel with per-block self-guess + in-kernel verification.
//   Prologue: each block samples its first 4-way batch (16K int32) ->
//   per-block pack; applies it while streaming. True max published via one
//   atomicMax; pack votes via atomicMin/Max. The LAST finishing block checks
//   that every vote equals the actual pack; on the (astronomically rare)
//   mismatch it rewrites all outputs itself -> result always exactly correct.
// ---------------------------------------------------------------------------
__global__ void uw_main_kernel(
    const int4* __restrict__ w4,
    const int4* __restrict__ g4,
    float4* __restrict__ ow4,
    float4* __restrict__ og4,
    const int* __restrict__ p_err_exp,
    const int* __restrict__ p_act_in_exp,
    const int* __restrict__ p_mu,
    float* __restrict__ out_exp,
    long n4)
{
    __shared__ unsigned s_red[32];
    __shared__ unsigned s_pack;
    __shared__ unsigned s_last;
    __shared__ unsigned s_fix;   // actual pack when fixup needed, else ~0

    const long S  = (long)gridDim.x * blockDim.x;
    const long i0 = (long)blockIdx.x * blockDim.x + threadIdx.x;
    int mu = decode_scalar(p_mu, 7);

    unsigned m = 0u;
    long i = i0;
    int4 g0, g1, g2, g3, w0, w1, w2, w3;
    const bool full = (i + 3 * S < n4);

    // ---- Prologue: first batch max (loads kept live in registers) ----
    if (full) {
        g0 = __ldg(&g4[i]);
        g1 = __ldg(&g4[i +     S]);
        g2 = __ldg(&g4[i + 2 * S]);
        g3 = __ldg(&g4[i + 3 * S]);
        w0 = __ldg(&w4[i]);
        w1 = __ldg(&w4[i +     S]);
        w2 = __ldg(&w4[i + 2 * S]);
        w3 = __ldg(&w4[i + 3 * S]);
        m = max(max(max4abs(g0), max4abs(g1)),
                max(max4abs(g2), max4abs(g3)));
    } else {
        for (long j = i; j < n4; j += S)
            m = max(m, max4abs(__ldg(&g4[j])));
    }
    {
        unsigned bm = block_reduce_max256(m, s_red);
        if (threadIdx.x == 0) s_pack = make_pack(bm, mu);
        __syncthreads();
    }
    const unsigned pack = s_pack;
    const int mode = (int)(pack & 3u);
    const int s    = (int)(pack >> 2);

    // ---- Main stream ----
    if (full) {
        float4 ow, og;
        uw_apply(g0, w0, mode, s, ow, og); ow4[i]         = ow; og4[i]         = og;
        uw_apply(g1, w1, mode, s, ow, og); ow4[i +     S] = ow; og4[i +     S] = og;
        uw_apply(g2, w2, mode, s, ow, og); ow4[i + 2 * S] = ow; og4[i + 2 * S] = og;
        uw_apply(g3, w3, mode, s, ow, og); ow4[i + 3 * S] = ow; og4[i + 3 * S] = og;
        i += 4 * S;
        for (; i + 3 * S < n4; i += 4 * S) {
            int4 a0 = __ldg(&g4[i]);
            int4 a1 = __ldg(&g4[i +     S]);
            int4 a2 = __ldg(&g4[i + 2 * S]);
            int4 a3 = __ldg(&g4[i + 3 * S]);
            int4 b0 = __ldg(&w4[i]);
            int4 b1 = __ldg(&w4[i +     S]);
            int4 b2 = __ldg(&w4[i + 2 * S]);
            int4 b3 = __ldg(&w4[i + 3 * S]);
            m = max(m, max(max(max4abs(a0), max4abs(a1)),
                           max(max4abs(a2), max4abs(a3))));
            uw_apply(a0, b0, mode, s, ow, og); ow4[i]         = ow; og4[i]         = og;
            uw_apply(a1, b1, mode, s, ow, og); ow4[i +     S] = ow; og4[i +     S] = og;
            uw_apply(a2, b2, mode, s, ow, og); ow4[i + 2 * S] = ow; og4[i + 2 * S] = og;
            uw_apply(a3, b3, mode, s, ow, og); ow4[i + 3 * S] = ow; og4[i + 3 * S] = og;
        }
        for (; i < n4; i += S) {
            int4 gv = __ldg(&g4[i]);
            int4 wv = __ldg(&w4[i]);
            m = max(m, max4abs(gv));
            uw_apply(gv, wv, mode, s, ow, og);
            ow4[i] = ow;
            og4[i] = og;
        }
    } else {
        for (long j = i0; j < n4; j += S) {
            int4 gv = __ldg(&g4[j]);
            int4 wv = __ldg(&w4[j]);
            float4 ow, og;
            uw_apply(gv, wv, mode, s, ow, og);
            ow4[j] = ow;
            og4[j] = og;
        }
    }

    // ---- Epilogue: publish true max + vote; last block verifies ----
    unsigned bm = block_reduce_max256(m, s_red);
    if (threadIdx.x == 0) {
        atomicMax(&g_act_rng, bm);
        if (i0 < n4) {                       // only blocks that did work vote
            atomicMin(&g_packmin, pack);
            atomicMax(&g_packmax, pack);
        }
        __threadfence();
        unsigned t = atomicAdd(&g_mcnt, 1u);
        s_last = (t == (unsigned)(gridDim.x - 1)) ? 1u : 0u;
    }
    __syncthreads();
    if (s_last) {
        if (threadIdx.x == 0) {
            unsigned rng  = atomicAdd(&g_act_rng, 0u);
            unsigned pmin = atomicAdd(&g_packmin, 0u);
            unsigned pmax = atomicAdd(&g_packmax, 0u);
            unsigned act  = make_pack(rng, mu);
            s_fix = (pmin != act || pmax != act) ? act : 0xFFFFFFFFu;
            int amode = (int)(act & 3u);
            int gs    = (amode == 2) ? (int)(act >> 2) : 0;
            int ee = decode_scalar(p_err_exp, -10);
            int ae = decode_scalar(p_act_in_exp, -7);
            *out_exp = (float)(ee + gs + ae);
            // Self-reset for next launch.
            g_mcnt    = 0u;
            g_act_rng = 0u;
            g_packmin = 0xFFFFFFFFu;
            g_packmax = 0u;
        }
        __syncthreads();
        unsigned fixpack = s_fix;
        if (fixpack != 0xFFFFFFFFu) {
            // Astronomically rare slow path: this block alone rewrites all
            // outputs with the actual transform. Correct for ANY input.
            int fmode = (int)(fixpack & 3u);
            int fs    = (int)(fixpack >> 2);
            for (long j = threadIdx.x; j < n4; j += blockDim.x) {
                int4 gv = __ldg(&g4[j]);
                int4 wv = __ldg(&w4[j]);
                float4 ow, og;
                uw_apply(gv, wv, fmode, fs, ow, og);
                ow4[j] = ow;
                og4[j] = og;
            }
        }
    }
}

// ---------------------------------------------------------------------------
// Launch. Inputs: weight int32[N] (promoted int8), grad int32[N],
// err_exp, act_in_exp, mu (int32 scalars).
// Output: float32[2N+1] = concat(new_weight, grad, grad_exp).
// ---------------------------------------------------------------------------
extern "C" void kernel_launch(void* const* d_in, const int* in_sizes, int n_in,
                              void* d_out, int out_size)
{
    const int4* w4 = (const int4*)d_in[0];
    const int4* g4 = (const int4*)d_in[1];
    const int* p_err = (n_in > 2) ? (const int*)d_in[2] : nullptr;
    const int* p_act = (n_in > 3) ? (const int*)d_in[3] : nullptr;
    const int* p_mu  = (n_in > 4) ? (const int*)d_in[4] : nullptr;

    long N  = (long)in_sizes[0];
    long n4 = N >> 2;

    float* out   = (float*)d_out;
    float4* ow4  = (float4*)out;
    float4* og4  = (float4*)(out + N);
    float* out_e = out + 2 * N;

    uw_main_kernel<<<MAIN_BLOCKS, TPB>>>(w4, g4, ow4, og4,
                                         p_err, p_act, p_mu, out_e, n4);
}

// round 15
// speedup vs baseline: 1.4814x; 1.0045x over previous
#include <cuda_runtime.h>
#include <cuda_bf16.h>
#include <cstdint>

#define MAIN_BLOCKS 1184
#define TPB         256

// Device-global scratch (no allocations). All state self-resets every launch
// (last block restores it after use) -> deterministic, graph-safe.
__device__ unsigned g_act_rng  = 0u;
__device__ unsigned g_mcnt     = 0u;
__device__ unsigned g_packmin  = 0xFFFFFFFFu;
__device__ unsigned g_packmax  = 0u;

// ---------------------------------------------------------------------------
// Robust small-integer scalar decode (int32/int64/float32/float64).
// ---------------------------------------------------------------------------
__device__ __forceinline__ int decode_scalar(const int* p, int dflt) {
    if (p == nullptr) return dflt;
    int w0 = p[0];
    if (w0 >= -1000000 && w0 <= 1000000) {
        if (w0 != 0) return w0;
        int w1 = p[1];
        if (w1 == 0) return 0;
        double d = __hiloint2double(w1, w0);
        if (d >= -1e6 && d <= 1e6) return (int)d;
        return 0;
    }
    float f = __int_as_float(w0);
    if (f >= -1e6f && f <= 1e6f) return (int)f;
    int w1 = p[1];
    double d = __hiloint2double(w1, w0);
    if (d >= -1e6 && d <= 1e6) return (int)d;
    return dflt;
}

// Transform descriptor: pack = mode | (shift << 2)
//   mode 0 = zeros (bw==0), 1 = int8-wrap trunc (shift<1), 2 = psto(shift)
__device__ __forceinline__ unsigned make_pack(unsigned rng, int mu) {
    if (rng == 0u) return 0u;
    int bw = (int)ceilf(log2f(fmaxf((float)rng, 1.0f)));
    int shift = bw - mu;
    if (shift < 1) return 1u;
    return 2u | ((unsigned)shift << 2);
}

// Pseudo-stochastic shift quantizer (bit-exact vs reference, s >= 1).
__device__ __forceinline__ int uw_psto(int x, int s) {
    int rt   = x >> s;
    int prob = x & ((1 << s) - 1);
    int hs   = s >> 1;
    int qprob = prob >> hs;
    int prn   = (prob & ((1 << hs) - 1)) * (1 + (s & 1));
    int sgn   = (x > 0) - (x < 0);
    int dec   = (qprob <= prn) ? 0 : sgn;
    return min(127, max(-127, rt + dec));
}

__device__ __forceinline__ unsigned max4abs(int4 v) {
    unsigned a0 = (unsigned)(v.x < 0 ? -v.x : v.x);
    unsigned a1 = (unsigned)(v.y < 0 ? -v.y : v.y);
    unsigned a2 = (unsigned)(v.z < 0 ? -v.z : v.z);
    unsigned a3 = (unsigned)(v.w < 0 ? -v.w : v.w);
    return max(max(a0, a1), max(a2, a3));
}

__device__ __forceinline__ void uw_apply(int4 gv, int4 wv, int mode, int s,
                                         float4& ow, float4& og) {
    int gx[4] = { gv.x, gv.y, gv.z, gv.w };
    int wi[4] = { wv.x, wv.y, wv.z, wv.w };
    float o_g[4], o_w[4];
#pragma unroll
    for (int k = 0; k < 4; k++) {
        int gq;
        if (mode == 0)      gq = 0;
        else if (mode == 1) gq = (int)(signed char)gx[k];   // wraps like astype(int8)
        else                gq = uw_psto(gx[k], s);
        int nw = wi[k] - gq;
        nw = min(127, max(-127, nw));
        o_g[k] = (float)gq;
        o_w[k] = (float)nw;
    }
    ow = make_float4(o_w[0], o_w[1], o_w[2], o_w[3]);
    og = make_float4(o_g[0], o_g[1], o_g[2], o_g[3]);
}

__device__ __forceinline__ unsigned block_reduce_max256(unsigned m, unsigned* s_red) {
    m = __reduce_max_sync(0xffffffffu, m);
    int lane = threadIdx.x & 31;
    int wid  = threadIdx.x >> 5;
    if (lane == 0) s_red[wid] = m;
    __syncthreads();
    unsigned v = 0u;
    if (wid == 0) {
        v = (lane < (int)(blockDim.x >> 5)) ? s_red[lane] : 0u;
        v = __reduce_max_sync(0xffffffffu, v);
    }
    return v;  // valid in warp 0
}

// ---------------------------------------------------------------------------
// SINGLE fused kernel, per-block self-guess + in-kernel verification.
// Block-CONTIGUOUS 16KB chunks per array per iteration (k*TPB inner stride,
// 4*TPB*gridDim outer stride) for DRAM row-buffer locality.
// ---------------------------------------------------------------------------
__global__ void uw_main_kernel(
    const int4* __restrict__ w4,
    const int4* __restrict__ g4,
    float4* __restrict__ ow4,
    float4* __restrict__ og4,
    const int* __restrict__ p_err_exp,
    const int* __restrict__ p_act_in_exp,
    const int* __restrict__ p_mu,
    float* __restrict__ out_exp,
    long n4)
{
    __shared__ unsigned s_red[32];
    __shared__ unsigned s_pack;
    __shared__ unsigned s_last;
    __shared__ unsigned s_fix;   // actual pack when fixup needed, else ~0

    const int  T  = TPB;
    const long C  = 4L * T;                       // int4 per block-chunk
    const long S  = (long)gridDim.x * C;          // outer grid stride
    const long b0 = (long)blockIdx.x * C + threadIdx.x;
    int mu = decode_scalar(p_mu, 7);

    unsigned m = 0u;
    long i = b0;
    int4 g0, g1, g2, g3, w0, w1, w2, w3;
    const bool full = (i + 3 * T < n4);

    // ---- Prologue: first chunk max (loads kept live in registers) ----
    if (full) {
        g0 = __ldg(&g4[i]);
        g1 = __ldg(&g4[i +     T]);
        g2 = __ldg(&g4[i + 2 * T]);
        g3 = __ldg(&g4[i + 3 * T]);
        w0 = __ldg(&w4[i]);
        w1 = __ldg(&w4[i +     T]);
        w2 = __ldg(&w4[i + 2 * T]);
        w3 = __ldg(&w4[i + 3 * T]);
        m = max(max(max4abs(g0), max4abs(g1)),
                max(max4abs(g2), max4abs(g3)));
    } else {
        for (long j = i; j < n4; j += T)
            m = max(m, max4abs(__ldg(&g4[j])));
    }
    {
        unsigned bm = block_reduce_max256(m, s_red);
        if (threadIdx.x == 0) s_pack = make_pack(bm, mu);
        __syncthreads();
    }
    const unsigned pack = s_pack;
    const int mode = (int)(pack & 3u);
    const int s    = (int)(pack >> 2);

    // ---- Main stream ----
    if (full) {
        float4 ow, og;
        uw_apply(g0, w0, mode, s, ow, og); ow4[i]         = ow; og4[i]         = og;
        uw_apply(g1, w1, mode, s, ow, og); ow4[i +     T] = ow; og4[i +     T] = og;
        uw_apply(g2, w2, mode, s, ow, og); ow4[i + 2 * T] = ow; og4[i + 2 * T] = og;
        uw_apply(g3, w3, mode, s, ow, og); ow4[i + 3 * T] = ow; og4[i + 3 * T] = og;
        i += S;
        for (; i + 3 * T < n4; i += S) {
            int4 a0 = __ldg(&g4[i]);
            int4 a1 = __ldg(&g4[i +     T]);
            int4 a2 = __ldg(&g4[i + 2 * T]);
            int4 a3 = __ldg(&g4[i + 3 * T]);
            int4 b1_ = __ldg(&w4[i]);
            int4 b2_ = __ldg(&w4[i +     T]);
            int4 b3_ = __ldg(&w4[i + 2 * T]);
            int4 b4_ = __ldg(&w4[i + 3 * T]);
            m = max(m, max(max(max4abs(a0), max4abs(a1)),
                           max(max4abs(a2), max4abs(a3))));
            uw_apply(a0, b1_, mode, s, ow, og); ow4[i]         = ow; og4[i]         = og;
            uw_apply(a1, b2_, mode, s, ow, og); ow4[i +     T] = ow; og4[i +     T] = og;
            uw_apply(a2, b3_, mode, s, ow, og); ow4[i + 2 * T] = ow; og4[i + 2 * T] = og;
            uw_apply(a3, b4_, mode, s, ow, og); ow4[i + 3 * T] = ow; og4[i + 3 * T] = og;
        }
        // Tail: walk remaining chunk (if any) at T-stride.
        for (; i < n4; i += T) {
            int4 gv = __ldg(&g4[i]);
            int4 wv = __ldg(&w4[i]);
            m = max(m, max4abs(gv));
            uw_apply(gv, wv, mode, s, ow, og);
            ow4[i] = ow;
            og4[i] = og;
        }
    } else {
        for (long j = b0; j < n4; j += T) {
            int4 gv = __ldg(&g4[j]);
            int4 wv = __ldg(&w4[j]);
            float4 ow, og;
            uw_apply(gv, wv, mode, s, ow, og);
            ow4[j] = ow;
            og4[j] = og;
        }
    }

    // ---- Epilogue: publish true max + vote; last block verifies ----
    unsigned bm = block_reduce_max256(m, s_red);
    if (threadIdx.x == 0) {
        atomicMax(&g_act_rng, bm);
        if (b0 < n4) {                       // only blocks that did work vote
            atomicMin(&g_packmin, pack);
            atomicMax(&g_packmax, pack);
        }
        __threadfence();
        unsigned t = atomicAdd(&g_mcnt, 1u);
        s_last = (t == (unsigned)(gridDim.x - 1)) ? 1u : 0u;
    }
    __syncthreads();
    if (s_last) {
        if (threadIdx.x == 0) {
            unsigned rng  = atomicAdd(&g_act_rng, 0u);
            unsigned pmin = atomicAdd(&g_packmin, 0u);
            unsigned pmax = atomicAdd(&g_packmax, 0u);
            unsigned act  = make_pack(rng, mu);
            s_fix = (pmin != act || pmax != act) ? act : 0xFFFFFFFFu;
            int amode = (int)(act & 3u);
            int gs    = (amode == 2) ? (int)(act >> 2) : 0;
            int ee = decode_scalar(p_err_exp, -10);
            int ae = decode_scalar(p_act_in_exp, -7);
            *out_exp = (float)(ee + gs + ae);
            // Self-reset for next launch.
            g_mcnt    = 0u;
            g_act_rng = 0u;
            g_packmin = 0xFFFFFFFFu;
            g_packmax = 0u;
        }
        __syncthreads();
        unsigned fixpack = s_fix;
        if (fixpack != 0xFFFFFFFFu) {
            // Astronomically rare slow path: this block alone rewrites all
            // outputs with the actual transform. Correct for ANY input.
            int fmode = (int)(fixpack & 3u);
            int fs    = (int)(fixpack >> 2);
            for (long j = threadIdx.x; j < n4; j += blockDim.x) {
                int4 gv = __ldg(&g4[j]);
                int4 wv = __ldg(&w4[j]);
                float4 ow, og;
                uw_apply(gv, wv, fmode, fs, ow, og);
                ow4[j] = ow;
                og4[j] = og;
            }
        }
    }
}

// ---------------------------------------------------------------------------
// Launch. Inputs: weight int32[N] (promoted int8), grad int32[N],
// err_exp, act_in_exp, mu (int32 scalars).
// Output: float32[2N+1] = concat(new_weight, grad, grad_exp).
// ---------------------------------------------------------------------------
extern "C" void kernel_launch(void* const* d_in, const int* in_sizes, int n_in,
                              void* d_out, int out_size)
{
    const int4* w4 = (const int4*)d_in[0];
    const int4* g4 = (const int4*)d_in[1];
    const int* p_err = (n_in > 2) ? (const int*)d_in[2] : nullptr;
    const int* p_act = (n_in > 3) ? (const int*)d_in[3] : nullptr;
    const int* p_mu  = (n_in > 4) ? (const int*)d_in[4] : nullptr;

    long N  = (long)in_sizes[0];
    long n4 = N >> 2;

    float* out   = (float*)d_out;
    float4* ow4  = (float4*)out;
    float4* og4  = (float4*)(out + N);
    float* out_e = out + 2 * N;

    uw_main_kernel<<<MAIN_BLOCKS, TPB>>>(w4, g4, ow4, og4,
                                         p_err, p_act, p_mu, out_e, n4);
}